// round 11
// baseline (speedup 1.0000x reference)
#include <cuda.h>
#include <cuda_runtime.h>
#include <cuda_bf16.h>
#include <cstdint>
#include <math.h>

// ---------------------------------------------------------------------------
// GCN: 3x GCNConv(relu) + global_mean_pool + linear   (6-kernel pipeline)
//   hist+wprep -> scan(lookback) -> fill -> gemm2f -> gemm3f -> poolf
// GEMMs: mma.sync bf16 split (hi+lo), fp32 accumulators; fp32 message bufs.
// ---------------------------------------------------------------------------

#define MAXN 50000
#define MAXE 600000
#define H 128
#define GMAX 8
#define C 5

__device__ float g_bufB[MAXN * H];   // g2
__device__ float g_bufA[MAXN * H];   // g3
__device__ float4 g_gx[MAXN];        // {x0*dis, x1*dis, x2*dis, dis}
__device__ float g_dis[MAXN];
__device__ int   g_deg[MAXN];        // zeroed by poolf for next run
__device__ int   g_rowstart[MAXN + 1];
__device__ int   g_cursor[MAXN];
__device__ int   g_csrsrc[MAXE];
__device__ int   g_btotal[256];
__device__ int   g_sflag[256];       // zeroed by hist each run
__device__ float g_pool[128 * H];    // zeroed by poolf last block
__device__ float g_cnt[128];
__device__ int   g_done;
// W fragments: uint32 [16 nb][8 kb][32 lane][2 pair]
__device__ uint32_t g_w2hi[8192], g_w2lo[8192];
__device__ uint32_t g_w3hi[8192], g_w3lo[8192];

__device__ __forceinline__ int detect64(const void* p) {
    const unsigned int* w = (const unsigned int*)p;
    int lane = threadIdx.x & 31;
    unsigned int a = w[2 * lane + 1] | w[2 * (lane + 32) + 1];
    unsigned int nz = __ballot_sync(0xffffffffu, a != 0u);
    return nz == 0u;
}
__device__ __forceinline__ int getIdx(const void* p, long long i, int flag64) {
    if (flag64) return (int)((const long long*)p)[i];
    return ((const int*)p)[i];
}
// 4 consecutive indices starting at e0 (e0 % 4 == 0), from typed base
__device__ __forceinline__ void load4(const void* p, long long base, int e0,
                                      int flag64, int* d) {
    if (flag64) {
        const ulonglong2* q = (const ulonglong2*)((const long long*)p + base + e0);
        ulonglong2 a = q[0], b = q[1];
        d[0] = (int)a.x; d[1] = (int)a.y; d[2] = (int)b.x; d[3] = (int)b.y;
    } else {
        int4 v = *(const int4*)((const int*)p + base + e0);
        d[0] = v.x; d[1] = v.y; d[2] = v.z; d[3] = v.w;
    }
}
__device__ __forceinline__ uint32_t smem_u32(const void* p) {
    uint32_t a;
    asm("{ .reg .u64 t; cvta.to.shared.u64 t, %1; cvt.u32.u64 %0, t; }"
        : "=r"(a) : "l"(p));
    return a;
}

// ======================= mma.sync bf16 GEMM core ============================
// Block: 64 rows x 128 cols, 256 thr, 8 warps (2m x 4n), warp tile 32x32.
#define APAD 136
#define S_AHI 0
#define S_ALO (64 * APAD * 2)            // 17408
#define S_TOTAL (2 * 64 * APAD * 2)      // 34816

__device__ __forceinline__ void ldsm4(uint32_t* r, uint32_t addr) {
    asm volatile("ldmatrix.sync.aligned.m8n8.x4.shared.b16 {%0,%1,%2,%3}, [%4];"
                 : "=r"(r[0]), "=r"(r[1]), "=r"(r[2]), "=r"(r[3]) : "r"(addr));
}
__device__ __forceinline__ void mma16816(float* c, const uint32_t* a,
                                         uint32_t b0, uint32_t b1) {
    asm volatile("mma.sync.aligned.m16n8k16.row.col.f32.bf16.bf16.f32 "
                 "{%0,%1,%2,%3}, {%4,%5,%6,%7}, {%8,%9}, {%0,%1,%2,%3};"
                 : "+f"(c[0]), "+f"(c[1]), "+f"(c[2]), "+f"(c[3])
                 : "r"(a[0]), "r"(a[1]), "r"(a[2]), "r"(a[3]), "r"(b0), "r"(b1));
}
__device__ __forceinline__ void split_pack(float x, float y,
                                           uint32_t& hp, uint32_t& lp) {
    __nv_bfloat16 hx = __float2bfloat16(x);
    __nv_bfloat16 hy = __float2bfloat16(y);
    __nv_bfloat16 lx = __float2bfloat16(x - __bfloat162float(hx));
    __nv_bfloat16 ly = __float2bfloat16(y - __bfloat162float(hy));
    hp = (uint32_t)__bfloat16_as_ushort(hx) | ((uint32_t)__bfloat16_as_ushort(hy) << 16);
    lp = (uint32_t)__bfloat16_as_ushort(lx) | ((uint32_t)__bfloat16_as_ushort(ly) << 16);
}
__device__ __forceinline__ void store_Arow(char* sm, int r, int lane, float4 h) {
    uint32_t hp01, lp01, hp23, lp23;
    split_pack(h.x, h.y, hp01, lp01);
    split_pack(h.z, h.w, hp23, lp23);
    size_t boff = ((size_t)r * APAD + lane * 4) * 2;   // 8B aligned
    *(uint2*)(sm + S_AHI + boff) = make_uint2(hp01, hp23);
    *(uint2*)(sm + S_ALO + boff) = make_uint2(lp01, lp23);
}

// mainloop + epilogue (Out[row] *= g_dis[row]); B from global fragments
__device__ __forceinline__ void mma_main(uint32_t sb,
                                         const uint32_t* __restrict__ whi,
                                         const uint32_t* __restrict__ wlo,
                                         float* __restrict__ Out,
                                         int m0, int N, int wid, int lane) {
    int wm = wid & 1, wn = wid >> 1;
    float acc[2][4][4];
#pragma unroll
    for (int mi = 0; mi < 2; mi++)
#pragma unroll
        for (int ni = 0; ni < 4; ni++)
#pragma unroll
            for (int q = 0; q < 4; q++) acc[mi][ni][q] = 0.f;

    int quad = lane >> 3, l7 = lane & 7;
    uint32_t aRow = (uint32_t)(wm * 32 + (quad & 1) * 8 + l7);
    uint32_t aK   = (uint32_t)((quad >> 1) * 8);
    uint32_t aOff = (aRow * APAD + aK) * 2;

    const uint32_t aBase[3] = {S_AHI, S_ALO, S_AHI};
    const uint32_t* wB[3] = {wlo, whi, whi};
#pragma unroll
    for (int s = 0; s < 3; s++) {
        uint32_t aAddr = sb + aBase[s] + aOff;
        const uint2* wb = (const uint2*)wB[s];
#pragma unroll
        for (int ks = 0; ks < 8; ks++) {
            uint32_t a0[4], a1[4];
            ldsm4(a0, aAddr + ks * 32);
            ldsm4(a1, aAddr + (16 * APAD) * 2 + ks * 32);
            uint2 b0 = wb[((wn * 4 + 0) * 8 + ks) * 32 + lane];
            uint2 b1 = wb[((wn * 4 + 1) * 8 + ks) * 32 + lane];
            uint2 b2 = wb[((wn * 4 + 2) * 8 + ks) * 32 + lane];
            uint2 b3 = wb[((wn * 4 + 3) * 8 + ks) * 32 + lane];
            mma16816(acc[0][0], a0, b0.x, b0.y);
            mma16816(acc[0][1], a0, b1.x, b1.y);
            mma16816(acc[0][2], a0, b2.x, b2.y);
            mma16816(acc[0][3], a0, b3.x, b3.y);
            mma16816(acc[1][0], a1, b0.x, b0.y);
            mma16816(acc[1][1], a1, b1.x, b1.y);
            mma16816(acc[1][2], a1, b2.x, b2.y);
            mma16816(acc[1][3], a1, b3.x, b3.y);
        }
    }
    int g = lane >> 2, tig = lane & 3;
#pragma unroll
    for (int mi = 0; mi < 2; mi++) {
        int row0 = m0 + wm * 32 + mi * 16 + g;
        int row1 = row0 + 8;
        float d0 = (row0 < N) ? g_dis[row0] : 0.f;
        float d1 = (row1 < N) ? g_dis[row1] : 0.f;
#pragma unroll
        for (int ni = 0; ni < 4; ni++) {
            int col = wn * 32 + ni * 8 + tig * 2;
            if (row0 < N) {
                float2 v = make_float2(acc[mi][ni][0] * d0, acc[mi][ni][1] * d0);
                *(float2*)(Out + (size_t)row0 * H + col) = v;
            }
            if (row1 < N) {
                float2 v = make_float2(acc[mi][ni][2] * d1, acc[mi][ni][3] * d1);
                *(float2*)(Out + (size_t)row1 * H + col) = v;
            }
        }
    }
}

// --- gemm2f: layer1 (agg x -> project W1,b1,relu) fused as A-staging --------
__global__ __launch_bounds__(256, 3)
void gemm2f_kernel(const float* __restrict__ W1, const float* __restrict__ b1,
                   float* __restrict__ Out, int N) {
    extern __shared__ char sm[];
    uint32_t sb = smem_u32(sm);
    int tid = threadIdx.x, wid = tid >> 5, lane = tid & 31;
    int m0 = blockIdx.x * 64;

#pragma unroll 1
    for (int j = 0; j < 8; j++) {
        int r = wid * 8 + j;
        int v = m0 + r;
        float4 h = make_float4(0.f, 0.f, 0.f, 0.f);
        if (v < N) {
            int start = g_rowstart[v], end = g_rowstart[v + 1];
            float ax = 0.f, ay = 0.f, az = 0.f;
            for (int e = start + lane; e < end; e += 32) {
                int s = g_csrsrc[e];
                float4 gx = g_gx[s];
                ax += gx.x; ay += gx.y; az += gx.z;
            }
#pragma unroll
            for (int off = 16; off > 0; off >>= 1) {
                ax += __shfl_xor_sync(0xffffffffu, ax, off);
                ay += __shfl_xor_sync(0xffffffffu, ay, off);
                az += __shfl_xor_sync(0xffffffffu, az, off);
            }
            float4 self = g_gx[v];
            float d = self.w;
            float s0 = d * (ax + self.x);
            float s1 = d * (ay + self.y);
            float s2 = d * (az + self.z);
            float4 w0 = ((const float4*)(W1 + 0 * H))[lane];
            float4 w1 = ((const float4*)(W1 + 1 * H))[lane];
            float4 w2 = ((const float4*)(W1 + 2 * H))[lane];
            float4 bv = ((const float4*)b1)[lane];
            h.x = fmaxf(s0 * w0.x + s1 * w1.x + s2 * w2.x + bv.x, 0.f);
            h.y = fmaxf(s0 * w0.y + s1 * w1.y + s2 * w2.y + bv.y, 0.f);
            h.z = fmaxf(s0 * w0.z + s1 * w1.z + s2 * w2.z + bv.z, 0.f);
            h.w = fmaxf(s0 * w0.w + s1 * w1.w + s2 * w2.w + bv.w, 0.f);
        }
        store_Arow(sm, r, lane, h);
    }
    __syncthreads();
    mma_main(sb, g_w2hi, g_w2lo, Out, m0, N, wid, lane);
}

// --- gemm3f: aggregate(g2)+relu fused as A-staging --------------------------
__global__ __launch_bounds__(256, 3)
void gemm3f_kernel(const float* __restrict__ b2, const float* __restrict__ In,
                   float* __restrict__ Out, int N) {
    extern __shared__ char sm[];
    uint32_t sb = smem_u32(sm);
    int tid = threadIdx.x, wid = tid >> 5, lane = tid & 31;
    int m0 = blockIdx.x * 64;

#pragma unroll 1
    for (int j = 0; j < 8; j++) {
        int r = wid * 8 + j;
        int v = m0 + r;
        float4 h = make_float4(0.f, 0.f, 0.f, 0.f);
        if (v < N) {
            int start = g_rowstart[v], end = g_rowstart[v + 1];
            float4 a = make_float4(0.f, 0.f, 0.f, 0.f);
            for (int j0 = start; j0 < end; j0 += 32) {
                int nn = min(32, end - j0);
                int s = (j0 + lane < end) ? g_csrsrc[j0 + lane] : 0;
                for (int i = 0; i < nn; i++) {
                    int si = __shfl_sync(0xffffffffu, s, i);
                    float4 m = ((const float4*)(In + (size_t)si * H))[lane];
                    a.x += m.x; a.y += m.y; a.z += m.z; a.w += m.w;
                }
            }
            float4 gv = ((const float4*)(In + (size_t)v * H))[lane];
            float dv = g_dis[v];
            float4 bv = ((const float4*)b2)[lane];
            h.x = fmaxf(dv * (a.x + gv.x) + bv.x, 0.f);
            h.y = fmaxf(dv * (a.y + gv.y) + bv.y, 0.f);
            h.z = fmaxf(dv * (a.z + gv.z) + bv.z, 0.f);
            h.w = fmaxf(dv * (a.w + gv.w) + bv.w, 0.f);
        }
        store_Arow(sm, r, lane, h);
    }
    __syncthreads();
    mma_main(sb, g_w3hi, g_w3lo, Out, m0, N, wid, lane);
}

// ======================= graph preprocessing ================================

// hist + wprep merged: blocks [0, nbE4) histogram; blocks [nbE4, nbE4+64) wprep
__global__ void hist_kernel(const void* ei, int E, int nbE4,
                            const float* __restrict__ W2,
                            const float* __restrict__ W3) {
    int tid = threadIdx.x;
    if ((int)blockIdx.x >= nbE4) {
        int t = ((int)blockIdx.x - nbE4) * 256 + tid;
        if (t >= 16384) return;
        const float* W = (t & 8192) ? W3 : W2;
        uint32_t* dhi = (t & 8192) ? g_w3hi : g_w2hi;
        uint32_t* dlo = (t & 8192) ? g_w3lo : g_w2lo;
        int i = t & 8191;
        int pair = i & 1;
        int lane = (i >> 1) & 31;
        int kb = (i >> 6) & 7;
        int nb = i >> 9;
        int n = nb * 8 + (lane >> 2);
        int k = kb * 16 + (lane & 3) * 2 + pair * 8;
        uint32_t hp, lp;
        split_pack(W[k * H + n], W[(k + 1) * H + n], hp, lp);
        dhi[i] = hp;
        dlo[i] = lp;
        return;
    }
    int flag = detect64(ei);
    if (blockIdx.x == 0) g_sflag[tid & 255] = 0;
    int e0 = (blockIdx.x * 256 + tid) * 4;
    if (e0 + 3 < E) {
        int d[4];
        load4(ei, (long long)E, e0, flag, d);
#pragma unroll
        for (int j = 0; j < 4; j++) atomicAdd(&g_deg[d[j]], 1);
    } else {
        for (int j = 0; j < 4 && e0 + j < E; j++) {
            int dst = getIdx(ei, (long long)E + e0 + j, flag);
            atomicAdd(&g_deg[dst], 1);
        }
    }
}

__global__ void scan_kernel(const float* __restrict__ x, int N, int E) {
    __shared__ int ws[8];
    __shared__ int s_prev;
    int tid = threadIdx.x, lane = tid & 31, warp = tid >> 5;
    int bid = blockIdx.x;
    int base = bid * 1024 + tid * 4;
    int vals[4];
    int tsum = 0;
#pragma unroll
    for (int j = 0; j < 4; j++) {
        vals[j] = (base + j < N) ? g_deg[base + j] : 0;
        tsum += vals[j];
    }
    int incl = tsum;
#pragma unroll
    for (int off = 1; off < 32; off <<= 1) {
        int t = __shfl_up_sync(0xffffffffu, incl, off);
        if (lane >= off) incl += t;
    }
    if (lane == 31) ws[warp] = incl;
    __syncthreads();
    int wbase = 0, btot = 0;
#pragma unroll
    for (int i = 0; i < 8; i++) {
        int wv = ws[i];
        if (i < warp) wbase += wv;
        btot += wv;
    }
    if (tid == 0) {
        g_btotal[bid] = btot;
        __threadfence();
        ((volatile int*)g_sflag)[bid] = 1;
    }
    if (warp == 0) {
        int p = 0;
        for (int b = lane; b < bid; b += 32) {
            while (((volatile int*)g_sflag)[b] == 0) {}
            p += ((volatile int*)g_btotal)[b];
        }
#pragma unroll
        for (int off = 16; off > 0; off >>= 1)
            p += __shfl_xor_sync(0xffffffffu, p, off);
        if (lane == 0) s_prev = p;
    }
    __syncthreads();
    int offset = s_prev + wbase + (incl - tsum);
#pragma unroll
    for (int j = 0; j < 4; j++) {
        int idx = base + j;
        if (idx < N) {
            g_rowstart[idx] = offset;
            g_cursor[idx] = offset;
            float d = rsqrtf((float)(vals[j] + 1));
            g_dis[idx] = d;
            float4 gx;
            gx.x = x[idx * 3 + 0] * d;
            gx.y = x[idx * 3 + 1] * d;
            gx.z = x[idx * 3 + 2] * d;
            gx.w = d;
            g_gx[idx] = gx;
        }
        offset += vals[j];
    }
    if (bid == 0 && tid == 0) g_rowstart[N] = E;
}

__global__ void fill_kernel(const void* ei, int E) {
    int flag = detect64(ei);
    int e0 = (blockIdx.x * 256 + threadIdx.x) * 4;
    if (e0 + 3 < E) {
        int s[4], d[4];
        load4(ei, 0, e0, flag, s);
        load4(ei, (long long)E, e0, flag, d);
#pragma unroll
        for (int j = 0; j < 4; j++) {
            int pos = atomicAdd(&g_cursor[d[j]], 1);
            g_csrsrc[pos] = s[j];
        }
    } else {
        for (int j = 0; j < 4 && e0 + j < E; j++) {
            int src = getIdx(ei, e0 + j, flag);
            int dst = getIdx(ei, (long long)E + e0 + j, flag);
            int pos = atomicAdd(&g_cursor[dst], 1);
            g_csrsrc[pos] = src;
        }
    }
}

// ======================= fused agg3 + pool + final ==========================
__device__ __forceinline__ void pool_flush(int cur, int sbase, int G, int lane,
                                           float4 a, float c,
                                           float* sacc, float* scnt) {
    if (cur < 0) return;
    int gl = cur - sbase;
    if (gl >= 0 && gl < GMAX) {
        atomicAdd(&sacc[gl * H + lane * 4 + 0], a.x);
        atomicAdd(&sacc[gl * H + lane * 4 + 1], a.y);
        atomicAdd(&sacc[gl * H + lane * 4 + 2], a.z);
        atomicAdd(&sacc[gl * H + lane * 4 + 3], a.w);
        if (lane == 0) atomicAdd(&scnt[gl], c);
    } else if (cur < G) {
        atomicAdd(&g_pool[cur * H + lane * 4 + 0], a.x);
        atomicAdd(&g_pool[cur * H + lane * 4 + 1], a.y);
        atomicAdd(&g_pool[cur * H + lane * 4 + 2], a.z);
        atomicAdd(&g_pool[cur * H + lane * 4 + 3], a.w);
        if (lane == 0) atomicAdd(&g_cnt[cur], c);
    }
}

__global__ void poolf_kernel(const float* __restrict__ g3,
                             const float* __restrict__ b3,
                             const void* batchp, const void* ei,
                             const float* __restrict__ Wl,
                             const float* __restrict__ bl,
                             float* __restrict__ out, int N, int G) {
    __shared__ float sacc[GMAX * H];
    __shared__ float scnt[GMAX];
    __shared__ int s_last;
    int tid = threadIdx.x, w = tid >> 5, lane = tid & 31;
    int flag = detect64(ei);   // batch shares dtype with edge_index
    int n0 = blockIdx.x * 128;

    for (int i = tid; i < GMAX * H; i += 256) sacc[i] = 0.f;
    if (tid < GMAX) scnt[tid] = 0.f;
    for (int i = tid; i < 128; i += 256) {
        int v = n0 + i;
        if (v < N) g_deg[v] = 0;
    }
    int sbase = getIdx(batchp, min(n0, N - 1), flag);
    __syncthreads();

    float4 racc = make_float4(0.f, 0.f, 0.f, 0.f);
    float rc = 0.f;
    int cur = -1;
    float4 bv = ((const float4*)b3)[lane];
    for (int t = 0; t < 16; t++) {
        int v = n0 + w * 16 + t;
        if (v >= N) break;
        int gI = getIdx(batchp, v, flag);
        if (gI != cur) {
            pool_flush(cur, sbase, G, lane, racc, rc, sacc, scnt);
            cur = gI;
            racc = make_float4(0.f, 0.f, 0.f, 0.f);
            rc = 0.f;
        }
        float4 a = make_float4(0.f, 0.f, 0.f, 0.f);
        int start = g_rowstart[v], end = g_rowstart[v + 1];
        for (int j0 = start; j0 < end; j0 += 32) {
            int nn = min(32, end - j0);
            int s = (j0 + lane < end) ? g_csrsrc[j0 + lane] : 0;
            for (int i = 0; i < nn; i++) {
                int si = __shfl_sync(0xffffffffu, s, i);
                float4 m = ((const float4*)(g3 + (size_t)si * H))[lane];
                a.x += m.x; a.y += m.y; a.z += m.z; a.w += m.w;
            }
        }
        float4 gv = ((const float4*)(g3 + (size_t)v * H))[lane];
        float dv = g_dis[v];
        racc.x += fmaxf(dv * (a.x + gv.x) + bv.x, 0.f);
        racc.y += fmaxf(dv * (a.y + gv.y) + bv.y, 0.f);
        racc.z += fmaxf(dv * (a.z + gv.z) + bv.z, 0.f);
        racc.w += fmaxf(dv * (a.w + gv.w) + bv.w, 0.f);
        rc += 1.f;
    }
    pool_flush(cur, sbase, G, lane, racc, rc, sacc, scnt);
    __syncthreads();

    for (int i = tid; i < GMAX * H; i += 256) {
        int gl = i >> 7;
        if (sbase + gl < G) {
            float val = sacc[i];
            if (val != 0.f) atomicAdd(&g_pool[(sbase + gl) * H + (i & 127)], val);
        }
    }
    if (tid < GMAX && sbase + tid < G && scnt[tid] != 0.f)
        atomicAdd(&g_cnt[sbase + tid], scnt[tid]);

    __threadfence();
    if (tid == 0) s_last = atomicAdd(&g_done, 1);
    __syncthreads();
    if (s_last == (int)gridDim.x - 1) {
        for (int idx = tid; idx < G * C; idx += 256) {
            int g = idx / C, c = idx % C;
            float cnt = __ldcg(&g_cnt[g]);
            float inv = 1.f / fmaxf(cnt, 1.f);
            float acc = 0.f;
#pragma unroll 8
            for (int k = 0; k < H; k++)
                acc += __ldcg(&g_pool[g * H + k]) * Wl[k * C + c];
            out[idx] = acc * inv + bl[c];
        }
        __syncthreads();
        for (int idx = tid; idx < G * H; idx += 256) g_pool[idx] = 0.f;
        if (tid < G) g_cnt[tid] = 0.f;
        if (tid == 0) g_done = 0;
    }
}

// ---------------------------------------------------------------------------
extern "C" void kernel_launch(void* const* d_in, const int* in_sizes, int n_in,
                              void* d_out, int out_size) {
    const float* x  = (const float*)d_in[0];
    const void*  ei = d_in[1];
    const void*  bt = d_in[2];
    const float* W1 = (const float*)d_in[3];
    const float* b1 = (const float*)d_in[4];
    const float* W2 = (const float*)d_in[5];
    const float* b2 = (const float*)d_in[6];
    const float* W3 = (const float*)d_in[7];
    const float* b3 = (const float*)d_in[8];
    const float* Wl = (const float*)d_in[9];
    const float* bl = (const float*)d_in[10];
    float* out = (float*)d_out;

    int N = in_sizes[0] / 3;
    int E = in_sizes[1] / 2;
    int G = out_size / C;
    if (N > MAXN) N = MAXN;
    if (E > MAXE) E = MAXE;

    cudaFuncSetAttribute(gemm2f_kernel,
                         cudaFuncAttributeMaxDynamicSharedMemorySize, S_TOTAL);
    cudaFuncSetAttribute(gemm3f_kernel,
                         cudaFuncAttributeMaxDynamicSharedMemorySize, S_TOTAL);

    float *bufA, *bufB;
    cudaGetSymbolAddress((void**)&bufA, g_bufA);
    cudaGetSymbolAddress((void**)&bufB, g_bufB);

    int nbE4 = (E + 1023) / 1024;       // 4 edges/thread
    int nbScan = (N + 1023) / 1024;     // <= 256, all co-resident
    int nbTile = (N + 63) / 64;
    int nbPool = (N + 127) / 128;

    hist_kernel<<<nbE4 + 64, 256>>>(ei, E, nbE4, W2, W3);
    scan_kernel<<<nbScan, 256>>>(x, N, E);
    fill_kernel<<<nbE4, 256>>>(ei, E);
    gemm2f_kernel<<<nbTile, 256, S_TOTAL>>>(W1, b1, bufB, N);        // -> g2
    gemm3f_kernel<<<nbTile, 256, S_TOTAL>>>(b2, bufB, bufA, N);      // -> g3
    poolf_kernel<<<nbPool, 256>>>(bufA, b3, bt, ei, Wl, bl, out, N, G);
}

// round 12
// speedup vs baseline: 1.1800x; 1.1800x over previous
#include <cuda.h>
#include <cuda_runtime.h>
#include <cuda_bf16.h>
#include <cstdint>
#include <math.h>

// ---------------------------------------------------------------------------
// GCN: 3x GCNConv(relu) + global_mean_pool + linear   (5-launch pipeline)
//   hist+wprep -> scan(lookback) -> fill -> gemm2f -> gemm3f -> poolf
// GEMMs: mma.sync bf16 split (hi+lo), fp32 accumulators; fp32 message bufs.
// ---------------------------------------------------------------------------

#define MAXN 50000
#define MAXE 600000
#define H 128
#define GMAX 8
#define C 5

__device__ float g_bufB[MAXN * H];   // g2
__device__ float g_bufA[MAXN * H];   // g3
__device__ float4 g_gx[MAXN];        // {x0*dis, x1*dis, x2*dis, dis}
__device__ float g_dis[MAXN];
__device__ int   g_deg[MAXN];        // zeroed by poolf for next run
__device__ int   g_rowstart[MAXN + 1];
__device__ int   g_cursor[MAXN];
__device__ int   g_csrsrc[MAXE];
__device__ int   g_btotal[256];
__device__ int   g_sflag[256];       // zeroed by hist each run
__device__ float g_pool[128 * H];    // zeroed by poolf last block
__device__ float g_cnt[128];
__device__ int   g_done;
// W fragments: uint32 [16 nb][8 kb][32 lane][2 pair]
__device__ uint32_t g_w2hi[8192], g_w2lo[8192];
__device__ uint32_t g_w3hi[8192], g_w3lo[8192];

__device__ __forceinline__ int detect64(const void* p) {
    const unsigned int* w = (const unsigned int*)p;
    int lane = threadIdx.x & 31;
    unsigned int a = w[2 * lane + 1] | w[2 * (lane + 32) + 1];
    unsigned int nz = __ballot_sync(0xffffffffu, a != 0u);
    return nz == 0u;
}
__device__ __forceinline__ int getIdx(const void* p, long long i, int flag64) {
    if (flag64) return (int)((const long long*)p)[i];
    return ((const int*)p)[i];
}
// 4 consecutive indices starting at e0 (e0 % 4 == 0), from typed base
__device__ __forceinline__ void load4(const void* p, long long base, int e0,
                                      int flag64, int* d) {
    if (flag64) {
        const ulonglong2* q = (const ulonglong2*)((const long long*)p + base + e0);
        ulonglong2 a = q[0], b = q[1];
        d[0] = (int)a.x; d[1] = (int)a.y; d[2] = (int)b.x; d[3] = (int)b.y;
    } else {
        int4 v = *(const int4*)((const int*)p + base + e0);
        d[0] = v.x; d[1] = v.y; d[2] = v.z; d[3] = v.w;
    }
}
__device__ __forceinline__ uint32_t smem_u32(const void* p) {
    uint32_t a;
    asm("{ .reg .u64 t; cvta.to.shared.u64 t, %1; cvt.u32.u64 %0, t; }"
        : "=r"(a) : "l"(p));
    return a;
}

// ======================= mma.sync bf16 GEMM core ============================
// Block: 64 rows x 128 cols, 256 thr, 8 warps (2m x 4n), warp tile 32x32.
#define APAD 136
#define S_AHI 0
#define S_ALO (64 * APAD * 2)            // 17408
#define S_TOTAL (2 * 64 * APAD * 2)      // 34816

__device__ __forceinline__ void ldsm4(uint32_t* r, uint32_t addr) {
    asm volatile("ldmatrix.sync.aligned.m8n8.x4.shared.b16 {%0,%1,%2,%3}, [%4];"
                 : "=r"(r[0]), "=r"(r[1]), "=r"(r[2]), "=r"(r[3]) : "r"(addr));
}
__device__ __forceinline__ void mma16816(float* c, const uint32_t* a,
                                         uint32_t b0, uint32_t b1) {
    asm volatile("mma.sync.aligned.m16n8k16.row.col.f32.bf16.bf16.f32 "
                 "{%0,%1,%2,%3}, {%4,%5,%6,%7}, {%8,%9}, {%0,%1,%2,%3};"
                 : "+f"(c[0]), "+f"(c[1]), "+f"(c[2]), "+f"(c[3])
                 : "r"(a[0]), "r"(a[1]), "r"(a[2]), "r"(a[3]), "r"(b0), "r"(b1));
}
__device__ __forceinline__ void split_pack(float x, float y,
                                           uint32_t& hp, uint32_t& lp) {
    __nv_bfloat16 hx = __float2bfloat16(x);
    __nv_bfloat16 hy = __float2bfloat16(y);
    __nv_bfloat16 lx = __float2bfloat16(x - __bfloat162float(hx));
    __nv_bfloat16 ly = __float2bfloat16(y - __bfloat162float(hy));
    hp = (uint32_t)__bfloat16_as_ushort(hx) | ((uint32_t)__bfloat16_as_ushort(hy) << 16);
    lp = (uint32_t)__bfloat16_as_ushort(lx) | ((uint32_t)__bfloat16_as_ushort(ly) << 16);
}
__device__ __forceinline__ void store_Arow(char* sm, int r, int lane, float4 h) {
    uint32_t hp01, lp01, hp23, lp23;
    split_pack(h.x, h.y, hp01, lp01);
    split_pack(h.z, h.w, hp23, lp23);
    size_t boff = ((size_t)r * APAD + lane * 4) * 2;   // 8B aligned
    *(uint2*)(sm + S_AHI + boff) = make_uint2(hp01, hp23);
    *(uint2*)(sm + S_ALO + boff) = make_uint2(lp01, lp23);
}

// mainloop + epilogue (Out[row] *= g_dis[row]); B from global fragments
__device__ __forceinline__ void mma_main(uint32_t sb,
                                         const uint32_t* __restrict__ whi,
                                         const uint32_t* __restrict__ wlo,
                                         float* __restrict__ Out,
                                         int m0, int N, int wid, int lane) {
    int wm = wid & 1, wn = wid >> 1;
    float acc[2][4][4];
#pragma unroll
    for (int mi = 0; mi < 2; mi++)
#pragma unroll
        for (int ni = 0; ni < 4; ni++)
#pragma unroll
            for (int q = 0; q < 4; q++) acc[mi][ni][q] = 0.f;

    int quad = lane >> 3, l7 = lane & 7;
    uint32_t aRow = (uint32_t)(wm * 32 + (quad & 1) * 8 + l7);
    uint32_t aK   = (uint32_t)((quad >> 1) * 8);
    uint32_t aOff = (aRow * APAD + aK) * 2;

    const uint32_t aBase[3] = {S_AHI, S_ALO, S_AHI};
    const uint32_t* wB[3] = {wlo, whi, whi};
#pragma unroll
    for (int s = 0; s < 3; s++) {
        uint32_t aAddr = sb + aBase[s] + aOff;
        const uint2* wb = (const uint2*)wB[s];
#pragma unroll
        for (int ks = 0; ks < 8; ks++) {
            uint32_t a0[4], a1[4];
            ldsm4(a0, aAddr + ks * 32);
            ldsm4(a1, aAddr + (16 * APAD) * 2 + ks * 32);
            uint2 b0 = wb[((wn * 4 + 0) * 8 + ks) * 32 + lane];
            uint2 b1 = wb[((wn * 4 + 1) * 8 + ks) * 32 + lane];
            uint2 b2 = wb[((wn * 4 + 2) * 8 + ks) * 32 + lane];
            uint2 b3 = wb[((wn * 4 + 3) * 8 + ks) * 32 + lane];
            mma16816(acc[0][0], a0, b0.x, b0.y);
            mma16816(acc[0][1], a0, b1.x, b1.y);
            mma16816(acc[0][2], a0, b2.x, b2.y);
            mma16816(acc[0][3], a0, b3.x, b3.y);
            mma16816(acc[1][0], a1, b0.x, b0.y);
            mma16816(acc[1][1], a1, b1.x, b1.y);
            mma16816(acc[1][2], a1, b2.x, b2.y);
            mma16816(acc[1][3], a1, b3.x, b3.y);
        }
    }
    int g = lane >> 2, tig = lane & 3;
#pragma unroll
    for (int mi = 0; mi < 2; mi++) {
        int row0 = m0 + wm * 32 + mi * 16 + g;
        int row1 = row0 + 8;
        float d0 = (row0 < N) ? g_dis[row0] : 0.f;
        float d1 = (row1 < N) ? g_dis[row1] : 0.f;
#pragma unroll
        for (int ni = 0; ni < 4; ni++) {
            int col = wn * 32 + ni * 8 + tig * 2;
            if (row0 < N) {
                float2 v = make_float2(acc[mi][ni][0] * d0, acc[mi][ni][1] * d0);
                *(float2*)(Out + (size_t)row0 * H + col) = v;
            }
            if (row1 < N) {
                float2 v = make_float2(acc[mi][ni][2] * d1, acc[mi][ni][3] * d1);
                *(float2*)(Out + (size_t)row1 * H + col) = v;
            }
        }
    }
}

// dual-accumulator row gather: 2 independent FADD chains
__device__ __forceinline__ void gather_rows(const float* __restrict__ In,
                                            int start, int end, int lane,
                                            float4& out) {
    float4 a0 = make_float4(0.f, 0.f, 0.f, 0.f);
    float4 a1 = make_float4(0.f, 0.f, 0.f, 0.f);
    for (int j0 = start; j0 < end; j0 += 32) {
        int nn = min(32, end - j0);
        int s = (j0 + lane < end) ? g_csrsrc[j0 + lane] : 0;
        int i = 0;
        for (; i + 1 < nn; i += 2) {
            int si0 = __shfl_sync(0xffffffffu, s, i);
            int si1 = __shfl_sync(0xffffffffu, s, i + 1);
            float4 m0 = ((const float4*)(In + (size_t)si0 * H))[lane];
            float4 m1 = ((const float4*)(In + (size_t)si1 * H))[lane];
            a0.x += m0.x; a0.y += m0.y; a0.z += m0.z; a0.w += m0.w;
            a1.x += m1.x; a1.y += m1.y; a1.z += m1.z; a1.w += m1.w;
        }
        if (i < nn) {
            int si = __shfl_sync(0xffffffffu, s, i);
            float4 m = ((const float4*)(In + (size_t)si * H))[lane];
            a0.x += m.x; a0.y += m.y; a0.z += m.z; a0.w += m.w;
        }
    }
    out.x = a0.x + a1.x; out.y = a0.y + a1.y;
    out.z = a0.z + a1.z; out.w = a0.w + a1.w;
}

// --- gemm2f: layer1 (agg x -> project W1,b1,relu) fused as A-staging --------
__global__ __launch_bounds__(256, 2)
void gemm2f_kernel(const float* __restrict__ W1, const float* __restrict__ b1,
                   float* __restrict__ Out, int N) {
    extern __shared__ char sm[];
    uint32_t sb = smem_u32(sm);
    int tid = threadIdx.x, wid = tid >> 5, lane = tid & 31;
    int m0 = blockIdx.x * 64;

#pragma unroll 1
    for (int j = 0; j < 8; j++) {
        int r = wid * 8 + j;
        int v = m0 + r;
        float4 h = make_float4(0.f, 0.f, 0.f, 0.f);
        if (v < N) {
            int start = g_rowstart[v], end = g_rowstart[v + 1];
            float ax = 0.f, ay = 0.f, az = 0.f;
            for (int e = start + lane; e < end; e += 32) {
                int s = g_csrsrc[e];
                float4 gx = g_gx[s];
                ax += gx.x; ay += gx.y; az += gx.z;
            }
#pragma unroll
            for (int off = 16; off > 0; off >>= 1) {
                ax += __shfl_xor_sync(0xffffffffu, ax, off);
                ay += __shfl_xor_sync(0xffffffffu, ay, off);
                az += __shfl_xor_sync(0xffffffffu, az, off);
            }
            float4 self = g_gx[v];
            float d = self.w;
            float s0 = d * (ax + self.x);
            float s1 = d * (ay + self.y);
            float s2 = d * (az + self.z);
            float4 w0 = ((const float4*)(W1 + 0 * H))[lane];
            float4 w1 = ((const float4*)(W1 + 1 * H))[lane];
            float4 w2 = ((const float4*)(W1 + 2 * H))[lane];
            float4 bv = ((const float4*)b1)[lane];
            h.x = fmaxf(s0 * w0.x + s1 * w1.x + s2 * w2.x + bv.x, 0.f);
            h.y = fmaxf(s0 * w0.y + s1 * w1.y + s2 * w2.y + bv.y, 0.f);
            h.z = fmaxf(s0 * w0.z + s1 * w1.z + s2 * w2.z + bv.z, 0.f);
            h.w = fmaxf(s0 * w0.w + s1 * w1.w + s2 * w2.w + bv.w, 0.f);
        }
        store_Arow(sm, r, lane, h);
    }
    __syncthreads();
    mma_main(sb, g_w2hi, g_w2lo, Out, m0, N, wid, lane);
}

// --- gemm3f: aggregate(g2)+relu fused as A-staging --------------------------
__global__ __launch_bounds__(256, 2)
void gemm3f_kernel(const float* __restrict__ b2, const float* __restrict__ In,
                   float* __restrict__ Out, int N) {
    extern __shared__ char sm[];
    uint32_t sb = smem_u32(sm);
    int tid = threadIdx.x, wid = tid >> 5, lane = tid & 31;
    int m0 = blockIdx.x * 64;

#pragma unroll 1
    for (int j = 0; j < 8; j++) {
        int r = wid * 8 + j;
        int v = m0 + r;
        float4 h = make_float4(0.f, 0.f, 0.f, 0.f);
        if (v < N) {
            float4 a;
            gather_rows(In, g_rowstart[v], g_rowstart[v + 1], lane, a);
            float4 gv = ((const float4*)(In + (size_t)v * H))[lane];
            float dv = g_dis[v];
            float4 bv = ((const float4*)b2)[lane];
            h.x = fmaxf(dv * (a.x + gv.x) + bv.x, 0.f);
            h.y = fmaxf(dv * (a.y + gv.y) + bv.y, 0.f);
            h.z = fmaxf(dv * (a.z + gv.z) + bv.z, 0.f);
            h.w = fmaxf(dv * (a.w + gv.w) + bv.w, 0.f);
        }
        store_Arow(sm, r, lane, h);
    }
    __syncthreads();
    mma_main(sb, g_w3hi, g_w3lo, Out, m0, N, wid, lane);
}

// ======================= graph preprocessing ================================

// hist + wprep merged: blocks [0, nbE4) histogram; blocks [nbE4, nbE4+64) wprep
__global__ void hist_kernel(const void* ei, int E, int nbE4,
                            const float* __restrict__ W2,
                            const float* __restrict__ W3) {
    int tid = threadIdx.x;
    if ((int)blockIdx.x >= nbE4) {
        int t = ((int)blockIdx.x - nbE4) * 256 + tid;
        if (t >= 16384) return;
        const float* W = (t & 8192) ? W3 : W2;
        uint32_t* dhi = (t & 8192) ? g_w3hi : g_w2hi;
        uint32_t* dlo = (t & 8192) ? g_w3lo : g_w2lo;
        int i = t & 8191;
        int pair = i & 1;
        int lane = (i >> 1) & 31;
        int kb = (i >> 6) & 7;
        int nb = i >> 9;
        int n = nb * 8 + (lane >> 2);
        int k = kb * 16 + (lane & 3) * 2 + pair * 8;
        uint32_t hp, lp;
        split_pack(W[k * H + n], W[(k + 1) * H + n], hp, lp);
        dhi[i] = hp;
        dlo[i] = lp;
        return;
    }
    int flag = detect64(ei);
    if (blockIdx.x == 0) g_sflag[tid & 255] = 0;
    int e0 = (blockIdx.x * 256 + tid) * 4;
    if (e0 + 3 < E) {
        int d[4];
        load4(ei, (long long)E, e0, flag, d);
#pragma unroll
        for (int j = 0; j < 4; j++) atomicAdd(&g_deg[d[j]], 1);
    } else {
        for (int j = 0; j < 4 && e0 + j < E; j++) {
            int dst = getIdx(ei, (long long)E + e0 + j, flag);
            atomicAdd(&g_deg[dst], 1);
        }
    }
}

__global__ void scan_kernel(const float* __restrict__ x, int N, int E) {
    __shared__ int ws[8];
    __shared__ int s_prev;
    int tid = threadIdx.x, lane = tid & 31, warp = tid >> 5;
    int bid = blockIdx.x;
    int base = bid * 1024 + tid * 4;
    int vals[4];
    int tsum = 0;
#pragma unroll
    for (int j = 0; j < 4; j++) {
        vals[j] = (base + j < N) ? g_deg[base + j] : 0;
        tsum += vals[j];
    }
    int incl = tsum;
#pragma unroll
    for (int off = 1; off < 32; off <<= 1) {
        int t = __shfl_up_sync(0xffffffffu, incl, off);
        if (lane >= off) incl += t;
    }
    if (lane == 31) ws[warp] = incl;
    __syncthreads();
    int wbase = 0, btot = 0;
#pragma unroll
    for (int i = 0; i < 8; i++) {
        int wv = ws[i];
        if (i < warp) wbase += wv;
        btot += wv;
    }
    if (tid == 0) {
        g_btotal[bid] = btot;
        __threadfence();
        ((volatile int*)g_sflag)[bid] = 1;
    }
    if (warp == 0) {
        int p = 0;
        for (int b = lane; b < bid; b += 32) {
            while (((volatile int*)g_sflag)[b] == 0) {}
            p += ((volatile int*)g_btotal)[b];
        }
#pragma unroll
        for (int off = 16; off > 0; off >>= 1)
            p += __shfl_xor_sync(0xffffffffu, p, off);
        if (lane == 0) s_prev = p;
    }
    __syncthreads();
    int offset = s_prev + wbase + (incl - tsum);
#pragma unroll
    for (int j = 0; j < 4; j++) {
        int idx = base + j;
        if (idx < N) {
            g_rowstart[idx] = offset;
            g_cursor[idx] = offset;
            float d = rsqrtf((float)(vals[j] + 1));
            g_dis[idx] = d;
            float4 gx;
            gx.x = x[idx * 3 + 0] * d;
            gx.y = x[idx * 3 + 1] * d;
            gx.z = x[idx * 3 + 2] * d;
            gx.w = d;
            g_gx[idx] = gx;
        }
        offset += vals[j];
    }
    if (bid == 0 && tid == 0) g_rowstart[N] = E;
}

__global__ void fill_kernel(const void* ei, int E) {
    int flag = detect64(ei);
    int e0 = (blockIdx.x * 256 + threadIdx.x) * 4;
    if (e0 + 3 < E) {
        int s[4], d[4];
        load4(ei, 0, e0, flag, s);
        load4(ei, (long long)E, e0, flag, d);
#pragma unroll
        for (int j = 0; j < 4; j++) {
            int pos = atomicAdd(&g_cursor[d[j]], 1);
            g_csrsrc[pos] = s[j];
        }
    } else {
        for (int j = 0; j < 4 && e0 + j < E; j++) {
            int src = getIdx(ei, e0 + j, flag);
            int dst = getIdx(ei, (long long)E + e0 + j, flag);
            int pos = atomicAdd(&g_cursor[dst], 1);
            g_csrsrc[pos] = src;
        }
    }
}

// ======================= fused agg3 + pool + final ==========================
__device__ __forceinline__ void pool_flush(int cur, int sbase, int G, int lane,
                                           float4 a, float c,
                                           float* sacc, float* scnt) {
    if (cur < 0) return;
    int gl = cur - sbase;
    if (gl >= 0 && gl < GMAX) {
        atomicAdd(&sacc[gl * H + lane * 4 + 0], a.x);
        atomicAdd(&sacc[gl * H + lane * 4 + 1], a.y);
        atomicAdd(&sacc[gl * H + lane * 4 + 2], a.z);
        atomicAdd(&sacc[gl * H + lane * 4 + 3], a.w);
        if (lane == 0) atomicAdd(&scnt[gl], c);
    } else if (cur < G) {
        atomicAdd(&g_pool[cur * H + lane * 4 + 0], a.x);
        atomicAdd(&g_pool[cur * H + lane * 4 + 1], a.y);
        atomicAdd(&g_pool[cur * H + lane * 4 + 2], a.z);
        atomicAdd(&g_pool[cur * H + lane * 4 + 3], a.w);
        if (lane == 0) atomicAdd(&g_cnt[cur], c);
    }
}

__global__ void poolf_kernel(const float* __restrict__ g3,
                             const float* __restrict__ b3,
                             const void* batchp, const void* ei,
                             const float* __restrict__ Wl,
                             const float* __restrict__ bl,
                             float* __restrict__ out, int N, int G) {
    __shared__ float sacc[GMAX * H];
    __shared__ float scnt[GMAX];
    __shared__ int s_last;
    int tid = threadIdx.x, w = tid >> 5, lane = tid & 31;
    int flag = detect64(ei);   // batch shares dtype with edge_index
    int n0 = blockIdx.x * 128;

    for (int i = tid; i < GMAX * H; i += 256) sacc[i] = 0.f;
    if (tid < GMAX) scnt[tid] = 0.f;
    for (int i = tid; i < 128; i += 256) {
        int v = n0 + i;
        if (v < N) g_deg[v] = 0;
    }
    int sbase = getIdx(batchp, min(n0, N - 1), flag);
    __syncthreads();

    float4 racc = make_float4(0.f, 0.f, 0.f, 0.f);
    float rc = 0.f;
    int cur = -1;
    float4 bv = ((const float4*)b3)[lane];
    for (int t = 0; t < 16; t++) {
        int v = n0 + w * 16 + t;
        if (v >= N) break;
        int gI = getIdx(batchp, v, flag);
        if (gI != cur) {
            pool_flush(cur, sbase, G, lane, racc, rc, sacc, scnt);
            cur = gI;
            racc = make_float4(0.f, 0.f, 0.f, 0.f);
            rc = 0.f;
        }
        float4 a;
        gather_rows(g3, g_rowstart[v], g_rowstart[v + 1], lane, a);
        float4 gv = ((const float4*)(g3 + (size_t)v * H))[lane];
        float dv = g_dis[v];
        racc.x += fmaxf(dv * (a.x + gv.x) + bv.x, 0.f);
        racc.y += fmaxf(dv * (a.y + gv.y) + bv.y, 0.f);
        racc.z += fmaxf(dv * (a.z + gv.z) + bv.z, 0.f);
        racc.w += fmaxf(dv * (a.w + gv.w) + bv.w, 0.f);
        rc += 1.f;
    }
    pool_flush(cur, sbase, G, lane, racc, rc, sacc, scnt);
    __syncthreads();

    for (int i = tid; i < GMAX * H; i += 256) {
        int gl = i >> 7;
        if (sbase + gl < G) {
            float val = sacc[i];
            if (val != 0.f) atomicAdd(&g_pool[(sbase + gl) * H + (i & 127)], val);
        }
    }
    if (tid < GMAX && sbase + tid < G && scnt[tid] != 0.f)
        atomicAdd(&g_cnt[sbase + tid], scnt[tid]);

    __threadfence();
    if (tid == 0) s_last = atomicAdd(&g_done, 1);
    __syncthreads();
    if (s_last == (int)gridDim.x - 1) {
        for (int idx = tid; idx < G * C; idx += 256) {
            int g = idx / C, c = idx % C;
            float cnt = __ldcg(&g_cnt[g]);
            float inv = 1.f / fmaxf(cnt, 1.f);
            float acc = 0.f;
#pragma unroll 8
            for (int k = 0; k < H; k++)
                acc += __ldcg(&g_pool[g * H + k]) * Wl[k * C + c];
            out[idx] = acc * inv + bl[c];
        }
        __syncthreads();
        for (int idx = tid; idx < G * H; idx += 256) g_pool[idx] = 0.f;
        if (tid < G) g_cnt[tid] = 0.f;
        if (tid == 0) g_done = 0;
    }
}

// ---------------------------------------------------------------------------
extern "C" void kernel_launch(void* const* d_in, const int* in_sizes, int n_in,
                              void* d_out, int out_size) {
    const float* x  = (const float*)d_in[0];
    const void*  ei = d_in[1];
    const void*  bt = d_in[2];
    const float* W1 = (const float*)d_in[3];
    const float* b1 = (const float*)d_in[4];
    const float* W2 = (const float*)d_in[5];
    const float* b2 = (const float*)d_in[6];
    const float* W3 = (const float*)d_in[7];
    const float* b3 = (const float*)d_in[8];
    const float* Wl = (const float*)d_in[9];
    const float* bl = (const float*)d_in[10];
    float* out = (float*)d_out;

    int N = in_sizes[0] / 3;
    int E = in_sizes[1] / 2;
    int G = out_size / C;
    if (N > MAXN) N = MAXN;
    if (E > MAXE) E = MAXE;

    cudaFuncSetAttribute(gemm2f_kernel,
                         cudaFuncAttributeMaxDynamicSharedMemorySize, S_TOTAL);
    cudaFuncSetAttribute(gemm3f_kernel,
                         cudaFuncAttributeMaxDynamicSharedMemorySize, S_TOTAL);

    float *bufA, *bufB;
    cudaGetSymbolAddress((void**)&bufA, g_bufA);
    cudaGetSymbolAddress((void**)&bufB, g_bufB);

    int nbE4 = (E + 1023) / 1024;       // 4 edges/thread
    int nbScan = (N + 1023) / 1024;     // <= 256, all co-resident
    int nbTile = (N + 63) / 64;
    int nbPool = (N + 127) / 128;

    hist_kernel<<<nbE4 + 64, 256>>>(ei, E, nbE4, W2, W3);
    scan_kernel<<<nbScan, 256>>>(x, N, E);
    fill_kernel<<<nbE4, 256>>>(ei, E);
    gemm2f_kernel<<<nbTile, 256, S_TOTAL>>>(W1, b1, bufB, N);        // -> g2
    gemm3f_kernel<<<nbTile, 256, S_TOTAL>>>(b2, bufB, bufA, N);      // -> g3
    poolf_kernel<<<nbPool, 256>>>(bufA, b3, bt, ei, Wl, bl, out, N, G);
}